// round 14
// baseline (speedup 1.0000x reference)
#include <cuda_runtime.h>
#include <cstdint>

#define BATCH 512
#define TLEN  512
#define S     64
#define NEG_INF -10000.0f
#define NTHR  128   // tid = 2*n + h ; n = next-tag, h = prev-half

typedef unsigned long long ull;

__device__ __forceinline__ ull ADD2(ull a, ull b) {
    ull r; asm("add.rn.f32x2 %0, %1, %2;" : "=l"(r) : "l"(a), "l"(b)); return r;
}
// mov.b64 pair split is register aliasing (0 instr).
__device__ __forceinline__ void UNPK(ull v, float& lo, float& hi) {
    unsigned int l, h;
    asm("mov.b64 {%0,%1}, %2;" : "=r"(l), "=r"(h) : "l"(v));
    lo = __uint_as_float(l); hi = __uint_as_float(h);
}

__global__ __launch_bounds__(NTHR) void viterbi_all(
    const float* __restrict__ logits,       // (B, T, S)
    const float* __restrict__ masks,        // (B, T)
    const float* __restrict__ transitions,  // (S, S) [next, prev]
    float* __restrict__ out)                // [0,B): path_score ; [B,...): best_seq
{
    const int b   = blockIdx.x;
    const int tid = threadIdx.x;
    const int n   = tid >> 1;     // next tag 0..63
    const int h   = tid & 1;      // prev half 0..1

    __shared__ __align__(16) float fvbuf[2][S];
    __shared__ __align__(16) float smask[TLEN];
    __shared__ __align__(16) unsigned char bp_s[(TLEN - 1) * S]; // 32704 B
    __shared__ unsigned char seq_s[TLEN];

    // ---- my 32 transitions (row n, half h) as 16 packed f32x2 (from L2) ----
    ull tr2[16];
    {
        const ulonglong2* tp =
            (const ulonglong2*)(transitions + n * S + h * 32);
#pragma unroll
        for (int i = 0; i < 8; i++) {
            ulonglong2 v = tp[i];
            tr2[2 * i] = v.x; tr2[2 * i + 1] = v.y;
        }
    }

    // ---- stage mask row (2 KB); init fv ----
    {
        const float4* ms = (const float4*)(masks + (size_t)b * TLEN);
        ((float4*)smask)[tid] = ms[tid];
        if (h == 0) fvbuf[0][n] = (n == 0) ? 0.0f : NEG_INF;
    }
    __syncthreads();

    const float* lg = logits + (size_t)b * TLEN * S;

    // ---- emission prefetch pipeline (depth 4) ----
    float fb[4];
#pragma unroll
    for (int i = 0; i < 4; i++) fb[i] = lg[(1 + i) * S + n];

    // =================== forward: tournament with FLOAT indices ===================
#pragma unroll 4
    for (int t = 1; t < TLEN; t++) {
        float feat = fb[0];
        fb[0] = fb[1]; fb[1] = fb[2]; fb[2] = fb[3];
        int tpi = t + 4; if (tpi > TLEN - 1) tpi = TLEN - 1;
        fb[3] = lg[tpi * S + n];

        float m = smask[t];

        const ulonglong2* fvp =
            (const ulonglong2*)(&fvbuf[(t - 1) & 1][32 * h]);

        // level 0: 16 packed adds -> 16 (value, float-index) pairs
        float v16[16], i16[16];
#pragma unroll
        for (int k = 0; k < 8; k++) {
            ulonglong2 F = fvp[k];          // fv[32h+4k .. 32h+4k+3]
            float lo0, hi0, lo1, hi1;
            UNPK(ADD2(F.x, tr2[2 * k]),     lo0, hi0);
            UNPK(ADD2(F.y, tr2[2 * k + 1]), lo1, hi1);
            const int p0 = 32 * h + 4 * k;
            v16[2 * k]     = fmaxf(lo0, hi0);
            i16[2 * k]     = (hi0 > lo0) ? (float)(p0 + 1) : (float)p0;
            v16[2 * k + 1] = fmaxf(lo1, hi1);
            i16[2 * k + 1] = (hi1 > lo1) ? (float)(p0 + 3) : (float)(p0 + 2);
        }
        // balanced tournament; 'a' side is lower p, strict > keeps a on tie;
        // indices carried as floats -> FSEL (float pipe) instead of integer SEL
        float v8[8], i8[8];
#pragma unroll
        for (int k = 0; k < 8; k++) {
            bool g = v16[2 * k + 1] > v16[2 * k];
            v8[k] = fmaxf(v16[2 * k], v16[2 * k + 1]);
            i8[k] = g ? i16[2 * k + 1] : i16[2 * k];
        }
        float v4[4], i4[4];
#pragma unroll
        for (int k = 0; k < 4; k++) {
            bool g = v8[2 * k + 1] > v8[2 * k];
            v4[k] = fmaxf(v8[2 * k], v8[2 * k + 1]);
            i4[k] = g ? i8[2 * k + 1] : i8[2 * k];
        }
        float v2[2], i2[2];
#pragma unroll
        for (int k = 0; k < 2; k++) {
            bool g = v4[2 * k + 1] > v4[2 * k];
            v2[k] = fmaxf(v4[2 * k], v4[2 * k + 1]);
            i2[k] = g ? i4[2 * k + 1] : i4[2 * k];
        }
        bool gf = v2[1] > v2[0];
        float v   = fmaxf(v2[0], v2[1]);
        float idx = gf ? i2[1] : i2[0];

        // merge the two prev halves: h=0 owns lower p range; strict > keeps it
        float vo = __shfl_xor_sync(0xffffffffu, v, 1);
        float io = __shfl_xor_sync(0xffffffffu, idx, 1);
        if (h == 0) {
            if (vo > v) { v = vo; idx = io; }
            bp_s[(t - 1) * S + n] = (unsigned char)(int)idx;
            // torch quirk: path_score = pre-feat vmax at n = S-1, last step
            if (t == TLEN - 1 && n == S - 1) out[b] = v;
            fvbuf[t & 1][n] = __fmaf_rn(feat, m, v);   // v + feat*m (fused OK:
            // NOTE: reference does vmax + feat*m with separate mul+add; keep exact:
        }
        __syncthreads();
    }

    // ---- backtrace walk in shared (single thread, LDS chain) ----
    if (tid == 0) {
        int tag = bp_s[(TLEN - 2) * S + (S - 1)];   // seed (torch quirk)
        for (int i = TLEN - 2; i >= 0; i--) {
            seq_s[i] = (unsigned char)tag;
            tag = bp_s[i * S + tag];
        }
    }
    __syncthreads();

    // ---- coalesced output ----
    float* o = out + BATCH + (size_t)b * (TLEN - 1);
    for (int i = tid; i < TLEN - 1; i += NTHR) o[i] = (float)seq_s[i];
}

extern "C" void kernel_launch(void* const* d_in, const int* in_sizes, int n_in,
                              void* d_out, int out_size)
{
    const float* logits      = (const float*)d_in[0];
    const float* masks       = (const float*)d_in[1];
    const float* transitions = (const float*)d_in[2];
    float* out = (float*)d_out;

    viterbi_all<<<BATCH, NTHR>>>(logits, masks, transitions, out);
}

// round 15
// speedup vs baseline: 1.1019x; 1.1019x over previous
#include <cuda_runtime.h>
#include <cstdint>

#define BATCH 512
#define TLEN  512
#define S     64
#define NEG_INF -10000.0f
#define NTHR  128   // tid = 2*n + h ; n = next-tag, h = prev-half

typedef unsigned long long ull;

__device__ __forceinline__ ull ADD2(ull a, ull b) {
    ull r; asm("add.rn.f32x2 %0, %1, %2;" : "=l"(r) : "l"(a), "l"(b)); return r;
}
// mov.b64 pair split is register aliasing (0 instr).
__device__ __forceinline__ void UNPK(ull v, float& lo, float& hi) {
    unsigned int l, h;
    asm("mov.b64 {%0,%1}, %2;" : "=r"(l), "=r"(h) : "l"(v));
    lo = __uint_as_float(l); hi = __uint_as_float(h);
}

__global__ __launch_bounds__(NTHR) void viterbi_all(
    const float* __restrict__ logits,       // (B, T, S)
    const float* __restrict__ masks,        // (B, T)
    const float* __restrict__ transitions,  // (S, S) [next, prev]
    float* __restrict__ out)                // [0,B): path_score ; [B,...): best_seq
{
    const int b   = blockIdx.x;
    const int tid = threadIdx.x;
    const int n   = tid >> 1;     // next tag 0..63
    const int h   = tid & 1;      // prev half 0..1

    __shared__ __align__(16) float fvbuf[2][S];
    __shared__ __align__(16) float smask[TLEN];
    __shared__ __align__(16) float tr_s[S * S];                  // 16 KB
    __shared__ __align__(16) unsigned char bp_s[(TLEN - 1) * S]; // 32704 B
    __shared__ unsigned char seq_s[TLEN];

    // ---- stage transitions to shared (for idx-recovery recompute) ----
    {
        const float4* ts = (const float4*)transitions;
        float4* td = (float4*)tr_s;
        for (int i = tid; i < S * S / 4; i += NTHR) td[i] = ts[i];
        const float4* ms = (const float4*)(masks + (size_t)b * TLEN);
        ((float4*)smask)[tid] = ms[tid];
        if (h == 0) fvbuf[0][n] = (n == 0) ? 0.0f : NEG_INF;
    }
    __syncthreads();

    // ---- my 32 transitions (row n, half h) as 16 packed f32x2 ----
    ull tr2[16];
    {
        const ulonglong2* tp = (const ulonglong2*)(tr_s + n * S + h * 32);
#pragma unroll
        for (int i = 0; i < 8; i++) {
            ulonglong2 v = tp[i];
            tr2[2 * i] = v.x; tr2[2 * i + 1] = v.y;
        }
    }

    const float* lg = logits + (size_t)b * TLEN * S;

    // ---- emission prefetch pipeline (depth 4) ----
    float fb[4];
#pragma unroll
    for (int i = 0; i < 4; i++) fb[i] = lg[(1 + i) * S + n];

    // ========= forward: value-only FMNMX tree + cheap argmax recovery =========
#pragma unroll 4
    for (int t = 1; t < TLEN; t++) {
        float feat = fb[0];
        fb[0] = fb[1]; fb[1] = fb[2]; fb[2] = fb[3];
        int tpi = t + 4; if (tpi > TLEN - 1) tpi = TLEN - 1;
        fb[3] = lg[tpi * S + n];

        float m = smask[t];
        const float* fvprev = fvbuf[(t - 1) & 1];
        const ulonglong2* fvp = (const ulonglong2*)(fvprev + 32 * h);

        // level 0: 16 packed adds -> v16[j] = max over pair j (p = 32h+2j, +1)
        float v16[16];
#pragma unroll
        for (int k = 0; k < 8; k++) {
            ulonglong2 F = fvp[k];
            float lo0, hi0, lo1, hi1;
            UNPK(ADD2(F.x, tr2[2 * k]),     lo0, hi0);
            UNPK(ADD2(F.y, tr2[2 * k + 1]), lo1, hi1);
            v16[2 * k]     = fmaxf(lo0, hi0);
            v16[2 * k + 1] = fmaxf(lo1, hi1);
        }
        // value tree only (no index bookkeeping): 15 more FMNMX
        float v8[8], v4[4];
#pragma unroll
        for (int k = 0; k < 8; k++) v8[k] = fmaxf(v16[2 * k], v16[2 * k + 1]);
#pragma unroll
        for (int k = 0; k < 4; k++) v4[k] = fmaxf(v8[2 * k], v8[2 * k + 1]);
        float v2a = fmaxf(v4[0], v4[1]);
        float v2b = fmaxf(v4[2], v4[3]);
        float vloc = fmaxf(v2a, v2b);

        // ---- argmax recovery (OFF the critical path; lowest p on ties) ----
        bool e0 = (v4[0] == vloc), e1 = (v4[1] == vloc), e2 = (v4[2] == vloc);
        int jh = e0 ? 0 : (e1 ? 1 : (e2 ? 2 : 3));
        float g0 = e0 ? v16[0] : (e1 ? v16[4] : (e2 ? v16[8]  : v16[12]));
        float g1 = e0 ? v16[1] : (e1 ? v16[5] : (e2 ? v16[9]  : v16[13]));
        float g2 = e0 ? v16[2] : (e1 ? v16[6] : (e2 ? v16[10] : v16[14]));
        bool f0 = (g0 == vloc), f1 = (g1 == vloc), f2 = (g2 == vloc);
        int jl = f0 ? 0 : (f1 ? 1 : (f2 ? 2 : 3));
        int q = jh * 4 + jl;                        // winning packed pair 0..15
        int plo = 32 * h + 2 * q;                   // its even candidate
        // recompute even candidate exactly (ADD2 halves == scalar FADD.rn)
        float clo = __fadd_rn(fvprev[plo], tr_s[n * S + plo]);
        int idx = plo + ((clo == vloc) ? 0 : 1);

        // merge the two prev halves: h=0 owns lower p; strict > keeps it on tie
        float vo = __shfl_xor_sync(0xffffffffu, vloc, 1);
        int   io = __shfl_xor_sync(0xffffffffu, idx, 1);
        if (h == 0) {
            float v = vloc; int ix = idx;
            if (vo > v) { v = vo; ix = io; }
            bp_s[(t - 1) * S + n] = (unsigned char)ix;
            // torch quirk: path_score = pre-feat vmax at n = S-1, last step
            if (t == TLEN - 1 && n == S - 1) out[b] = v;
            fvbuf[t & 1][n] = __fadd_rn(v, __fmul_rn(feat, m));
        }
        __syncthreads();
    }

    // ---- backtrace walk in shared (single thread, LDS chain) ----
    if (tid == 0) {
        int tag = bp_s[(TLEN - 2) * S + (S - 1)];   // seed (torch quirk)
        for (int i = TLEN - 2; i >= 0; i--) {
            seq_s[i] = (unsigned char)tag;
            tag = bp_s[i * S + tag];
        }
    }
    __syncthreads();

    // ---- coalesced output ----
    float* o = out + BATCH + (size_t)b * (TLEN - 1);
    for (int i = tid; i < TLEN - 1; i += NTHR) o[i] = (float)seq_s[i];
}

extern "C" void kernel_launch(void* const* d_in, const int* in_sizes, int n_in,
                              void* d_out, int out_size)
{
    const float* logits      = (const float*)d_in[0];
    const float* masks       = (const float*)d_in[1];
    const float* transitions = (const float*)d_in[2];
    float* out = (float*)d_out;

    viterbi_all<<<BATCH, NTHR>>>(logits, masks, transitions, out);
}